// round 15
// baseline (speedup 1.0000x reference)
#include <cuda_runtime.h>

#define CROP 512
#define GRID_N 8
#define NBINS 256
#define TILE 64        // CROP / GRID_N
#define SRC_W 640
#define SRC_H 640
#define NB 64          // batch
#define NWARP 8        // warps per block

// LUT scratch (values pre-divided by 255): 64 * 64 tiles * 256 bins * 4B = 4 MB
__device__ float g_luts[NB * GRID_N * GRID_N * NBINS];
// monotonic arrival / generation counters (NEVER reset; replay-safe)
__device__ unsigned g_cnt[NB];
__device__ unsigned g_gen[NB];

__device__ __forceinline__ float ldcg_f(const float* p) {
    float v;
    asm volatile("ld.global.cg.f32 %0, [%1];" : "=f"(v) : "l"(p));
    return v;
}

// ---------------------------------------------------------------------------
// Fused kernel: one block per (batch, tile). regs capped for 8 blocks/SM.
//  copy batch : stream the 64x64 output tile (flip-folded addressing).
//  clahe batch: STAGE 1: 16 loads -> bins packed in 4 regs (no atomics in
//               flight -> deep MLP). STAGE 2: 16 dependency-free atomicAdds
//               at ATOMS floor. -> clip/redistribute/scan -> publish LUT ->
//               per-batch generation barrier -> stage 4 quadrant float4
//               tables from 9 LUT vectors -> apply from retained bins.
// ---------------------------------------------------------------------------
__global__ void __launch_bounds__(256, 8)
clahe_fused_kernel(const float* __restrict__ x,
                   const int* __restrict__ hflip,
                   const int* __restrict__ vflip,
                   const int* __restrict__ offy,
                   const int* __restrict__ offx,
                   const int* __restrict__ apply_clahe,
                   float* __restrict__ out) {
    const int b    = blockIdx.x >> 6;
    const int tile = blockIdx.x & 63;
    const int ty   = tile >> 3;
    const int tx   = tile & 7;
    const int t    = threadIdx.x;         // 0..255

    const int   hf = hflip[b];
    const int   vf = vflip[b];
    const int   oy = offy[b];
    const int   ox = offx[b];
    const float* xb = x + (size_t)b * (SRC_W * SRC_H);

    // per-thread output-tile mapping: column j, rows i0+4k (k=0..15)
    const int j   = t & 63;
    const int i0  = t >> 6;
    const int gj  = tx * TILE + j;
    const int gi0 = ty * TILE + i0;

    // flip-folded source addressing
    const int rs      = vf ? -SRC_W : SRC_W;
    const int rowbase = vf ? (SRC_H - 1 - oy) : oy;
    const int sw      = hf ? (SRC_W - 1 - ox - gj) : (ox + gj);
    const float* p    = xb + rowbase * SRC_W + sw + gi0 * rs;
    const int pstep   = 4 * rs;

    float* q0 = out + ((size_t)b << 18) + (gi0 << 9) + gj;
    const int qstep = 4 << 9;

    if (!apply_clahe[b]) {
        // ---------------- copy path ----------------
        float* q = q0;
        #pragma unroll
        for (int k = 0; k < 16; k++) {
            __stcs(q, __ldg(p));
            p += pstep; q += qstep;
        }
        return;
    }

    // ---------------- clahe path ----------------
    __shared__ __align__(16) unsigned char smem_raw[4 * NBINS * 16];  // 16 KB
    __shared__ float wsum[NWARP];

    int (*hist)[NBINS] = (int (*)[NBINS])smem_raw;
    const int w    = t >> 5;
    const int lane = t & 31;

    // zero the 8 KB hist region with 2 STS.128 per thread
    {
        int4 z = make_int4(0, 0, 0, 0);
        int4* hz = (int4*)smem_raw;
        hz[t]       = z;
        hz[t + 256] = z;
    }
    __syncthreads();

    // STAGE 1: pure load/convert (deep MLP; no atomics on the chain)
    unsigned packed[4] = {0u, 0u, 0u, 0u};
    {
        const float* pA = p;
        const float* pB = p + 8 * pstep;
        #pragma unroll
        for (int k = 0; k < 8; k++) {
            float vA = __ldg(pA); pA += pstep;
            float vB = __ldg(pB); pB += pstep;
            unsigned bA = (unsigned)(int)(vA * (float)NBINS);  // [0,1) -> 0..255
            unsigned bB = (unsigned)(int)(vB * (float)NBINS);
            packed[k >> 2]       |= bA << ((k & 3) * 8);
            packed[2 + (k >> 2)] |= bB << ((k & 3) * 8);
        }
    }

    // STAGE 2: dependency-free atomic burst
    #pragma unroll
    for (int r = 0; r < 4; r++) {
        unsigned word = packed[r];
        atomicAdd(&hist[w][word & 255u], 1);
        atomicAdd(&hist[w][(word >> 8) & 255u], 1);
        atomicAdd(&hist[w][(word >> 16) & 255u], 1);
        atomicAdd(&hist[w][word >> 24], 1);
    }
    __syncthreads();

    // fold per-warp histograms; clip at 0.8*4096/256 = 12.8
    int hsum = 0;
    #pragma unroll
    for (int k = 0; k < NWARP; k++) hsum += hist[k][t];
    float clipped = fminf((float)hsum, 12.8f);

    // inclusive 256-thread scan (shuffle + 2 barriers)
    float v = clipped;
    #pragma unroll
    for (int s = 1; s < 32; s <<= 1) {
        float n = __shfl_up_sync(0xffffffffu, v, s);
        if (lane >= s) v += n;
    }
    if (lane == 31) wsum[w] = v;
    __syncthreads();
    if (w == 0 && lane < NWARP) {
        float ws = wsum[lane];
        #pragma unroll
        for (int s = 1; s < NWARP; s <<= 1) {
            float n = __shfl_up_sync(0xffu, ws, s);
            if (lane >= s) ws += n;
        }
        wsum[lane] = ws;
    }
    __syncthreads();

    float cum    = v + ((w > 0) ? wsum[w - 1] : 0.0f);
    float excess = 4096.0f - wsum[NWARP - 1];

    // lut = clip(cumsum(clipped + excess/256)/4096, 0, 1)
    float lut = (cum + excess * (float)(t + 1) * (1.0f / 256.0f)) * (1.0f / 4096.0f);
    lut = fminf(fmaxf(lut, 0.0f), 1.0f);
    g_luts[(((size_t)blockIdx.x) << 8) + t] = lut;

    // ---- per-batch generation barrier (monotonic, replay-safe) ----
    __syncthreads();                       // all LUT stores issued block-wide
    if (t == 0) {
        __threadfence();                   // publish this block's LUT stores
        unsigned my = atomicAdd(&g_cnt[b], 1u);
        unsigned target = (my >> 6) + 1u;  // this replay's cohort generation
        if ((my & 63u) == 63u)
            atomicAdd(&g_gen[b], 1u);      // 64th arriver releases the cohort
        while (*(volatile unsigned*)&g_gen[b] < target)
            __nanosleep(64);
        __threadfence();                   // acquire peers' LUT stores
    }
    __syncthreads();

    // stage 4 quadrant tables from 9 LUT vectors (own LUT from register)
    float4* T = (float4*)smem_raw;        // T[quadrant*256 + bin]
    {
        const int ya0 = max(ty - 1, 0), ya1 = ty, yb1 = min(ty + 1, GRID_N - 1);
        const int xa0 = max(tx - 1, 0), xa1 = tx, xb1 = min(tx + 1, GRID_N - 1);
        const float* lb = g_luts + ((size_t)b << 14);
        float l00 = ldcg_f(lb + ((ya0 * GRID_N + xa0) << 8) + t);
        float l01 = ldcg_f(lb + ((ya0 * GRID_N + xa1) << 8) + t);
        float l02 = ldcg_f(lb + ((ya0 * GRID_N + xb1) << 8) + t);
        float l10 = ldcg_f(lb + ((ya1 * GRID_N + xa0) << 8) + t);
        float l11 = lut;                   // this tile's own LUT
        float l12 = ldcg_f(lb + ((ya1 * GRID_N + xb1) << 8) + t);
        float l20 = ldcg_f(lb + ((yb1 * GRID_N + xa0) << 8) + t);
        float l21 = ldcg_f(lb + ((yb1 * GRID_N + xa1) << 8) + t);
        float l22 = ldcg_f(lb + ((yb1 * GRID_N + xb1) << 8) + t);
        T[0 * NBINS + t] = make_float4(l00, l01, l10, l11);   // qy=0, qx=0
        T[1 * NBINS + t] = make_float4(l01, l02, l11, l12);   // qy=0, qx=1
        T[2 * NBINS + t] = make_float4(l10, l11, l20, l21);   // qy=1, qx=0
        T[3 * NBINS + t] = make_float4(l11, l12, l21, l22);   // qy=1, qx=1
    }
    __syncthreads();

    // apply from retained bins (no input re-read)
    const int qx = j >> 5;
    const float fx = (qx ? ((float)j - 31.5f) : ((float)j + 32.5f)) * (1.0f / TILE);

    const float4* Ta = T + qx * NBINS;          // rows i < 32 (qy=0)
    const float4* Tb = T + (2 + qx) * NBINS;    // rows i >= 32 (qy=1)

    float* q = q0;
    float fy = ((float)i0 + 32.5f) * (1.0f / TILE);   // exact dyadic
    #pragma unroll
    for (int k = 0; k < 8; k++) {
        int bin = (packed[k >> 2] >> ((k & 3) * 8)) & 255;
        float4 tt = Ta[bin];
        float top = fmaf(fx, tt.y - tt.x, tt.x);
        float bot = fmaf(fx, tt.w - tt.z, tt.z);
        __stcs(q, fmaf(fy, bot - top, top));
        q += qstep; fy += (4.0f / TILE);
    }
    fy = ((float)i0 + 0.5f) * (1.0f / TILE);
    #pragma unroll
    for (int k = 8; k < 16; k++) {
        int bin = (packed[k >> 2] >> ((k & 3) * 8)) & 255;
        float4 tt = Tb[bin];
        float top = fmaf(fx, tt.y - tt.x, tt.x);
        float bot = fmaf(fx, tt.w - tt.z, tt.z);
        __stcs(q, fmaf(fy, bot - top, top));
        q += qstep; fy += (4.0f / TILE);
    }
}

extern "C" void kernel_launch(void* const* d_in, const int* in_sizes, int n_in,
                              void* d_out, int out_size) {
    const float* x          = (const float*)d_in[0];
    const int*   hflip      = (const int*)d_in[1];
    const int*   vflip      = (const int*)d_in[2];
    const int*   offy       = (const int*)d_in[3];
    const int*   offx       = (const int*)d_in[4];
    const int*   apply_clahe= (const int*)d_in[5];
    float*       out        = (float*)d_out;

    clahe_fused_kernel<<<NB * GRID_N * GRID_N, NBINS>>>(
        x, hflip, vflip, offy, offx, apply_clahe, out);
}

// round 16
// speedup vs baseline: 1.4099x; 1.4099x over previous
#include <cuda_runtime.h>

#define CROP 512
#define GRID_N 8
#define NBINS 256
#define TILE 64        // CROP / GRID_N
#define SRC_W 640
#define SRC_H 640
#define NB 64          // batch
#define NWARP 8        // warps per block

// LUT scratch (values pre-divided by 255): 64 * 64 tiles * 256 bins * 4B = 4 MB
__device__ float g_luts[NB * GRID_N * GRID_N * NBINS];
// per-tile monotonic done counters (NEVER reset; replay-safe)
__device__ unsigned g_done[NB * GRID_N * GRID_N];

__device__ __forceinline__ float ldcg_f(const float* p) {
    float v;
    asm volatile("ld.global.cg.f32 %0, [%1];" : "=f"(v) : "l"(p));
    return v;
}

// ---------------------------------------------------------------------------
// Fused kernel: one block per (batch, tile). regs capped for 8 blocks/SM.
//  copy batch : stream the 64x64 output tile (flip-folded addressing).
//  clahe batch: interleaved load+atomic histogram (LDG latency naturally
//               paces the ATOMS unit) + retain bins packed in regs ->
//               clip/redistribute/scan -> publish LUT -> wait on the <=8
//               NEIGHBOR tiles' done counters (not the whole 64-tile batch)
//               -> stage 4 quadrant float4 tables from 9 LUT vectors ->
//               apply from retained bins (no input re-read).
// ---------------------------------------------------------------------------
__global__ void __launch_bounds__(256, 8)
clahe_fused_kernel(const float* __restrict__ x,
                   const int* __restrict__ hflip,
                   const int* __restrict__ vflip,
                   const int* __restrict__ offy,
                   const int* __restrict__ offx,
                   const int* __restrict__ apply_clahe,
                   float* __restrict__ out) {
    const int b    = blockIdx.x >> 6;
    const int tile = blockIdx.x & 63;
    const int ty   = tile >> 3;
    const int tx   = tile & 7;
    const int t    = threadIdx.x;         // 0..255

    const int   hf = hflip[b];
    const int   vf = vflip[b];
    const int   oy = offy[b];
    const int   ox = offx[b];
    const float* xb = x + (size_t)b * (SRC_W * SRC_H);

    // per-thread output-tile mapping: column j, rows i0+4k (k=0..15)
    const int j   = t & 63;
    const int i0  = t >> 6;
    const int gj  = tx * TILE + j;
    const int gi0 = ty * TILE + i0;

    // flip-folded source addressing
    const int rs      = vf ? -SRC_W : SRC_W;
    const int rowbase = vf ? (SRC_H - 1 - oy) : oy;
    const int sw      = hf ? (SRC_W - 1 - ox - gj) : (ox + gj);
    const float* p    = xb + rowbase * SRC_W + sw + gi0 * rs;
    const int pstep   = 4 * rs;

    float* q0 = out + ((size_t)b << 18) + (gi0 << 9) + gj;
    const int qstep = 4 << 9;

    if (!apply_clahe[b]) {
        // ---------------- copy path ----------------
        float* q = q0;
        #pragma unroll
        for (int k = 0; k < 16; k++) {
            __stcs(q, __ldg(p));
            p += pstep; q += qstep;
        }
        return;
    }

    // ---------------- clahe path ----------------
    __shared__ __align__(16) unsigned char smem_raw[4 * NBINS * 16];  // 16 KB
    __shared__ float wsum[NWARP];

    int (*hist)[NBINS] = (int (*)[NBINS])smem_raw;
    const int w    = t >> 5;
    const int lane = t & 31;

    // zero the 8 KB hist region with 2 STS.128 per thread
    {
        int4 z = make_int4(0, 0, 0, 0);
        int4* hz = (int4*)smem_raw;
        hz[t]       = z;
        hz[t + 256] = z;
    }
    __syncthreads();

    // interleaved load + atomic histogram (two 8-chains), retain packed bins
    unsigned packed[4] = {0u, 0u, 0u, 0u};
    {
        const float* pA = p;
        const float* pB = p + 8 * pstep;
        #pragma unroll
        for (int k = 0; k < 8; k++) {
            float vA = __ldg(pA); pA += pstep;
            float vB = __ldg(pB); pB += pstep;
            int bA = (int)(vA * (float)NBINS);     // v in [0,1) -> 0..255
            int bB = (int)(vB * (float)NBINS);
            atomicAdd(&hist[w][bA], 1);
            atomicAdd(&hist[w][bB], 1);
            packed[k >> 2]       |= (unsigned)bA << ((k & 3) * 8);
            packed[2 + (k >> 2)] |= (unsigned)bB << ((k & 3) * 8);
        }
    }
    __syncthreads();

    // fold per-warp histograms; clip at 0.8*4096/256 = 12.8
    int hsum = 0;
    #pragma unroll
    for (int k = 0; k < NWARP; k++) hsum += hist[k][t];
    float clipped = fminf((float)hsum, 12.8f);

    // inclusive 256-thread scan (shuffle + 2 barriers)
    float v = clipped;
    #pragma unroll
    for (int s = 1; s < 32; s <<= 1) {
        float n = __shfl_up_sync(0xffffffffu, v, s);
        if (lane >= s) v += n;
    }
    if (lane == 31) wsum[w] = v;
    __syncthreads();
    if (w == 0 && lane < NWARP) {
        float ws = wsum[lane];
        #pragma unroll
        for (int s = 1; s < NWARP; s <<= 1) {
            float n = __shfl_up_sync(0xffu, ws, s);
            if (lane >= s) ws += n;
        }
        wsum[lane] = ws;
    }
    __syncthreads();

    float cum    = v + ((w > 0) ? wsum[w - 1] : 0.0f);
    float excess = 4096.0f - wsum[NWARP - 1];

    // lut = clip(cumsum(clipped + excess/256)/4096, 0, 1)
    float lut = (cum + excess * (float)(t + 1) * (1.0f / 256.0f)) * (1.0f / 4096.0f);
    lut = fminf(fmaxf(lut, 0.0f), 1.0f);
    g_luts[(((size_t)blockIdx.x) << 8) + t] = lut;

    // ---- neighbor-scope dependency wait (monotonic, replay-safe) ----
    // Each tile increments its own counter exactly once per launch, so after
    // launch N every counter equals N. target = my_old + 1 = this launch's N.
    __syncthreads();                       // all LUT stores issued block-wide
    if (t == 0) {
        __threadfence();                   // publish this block's LUT stores
        unsigned target = atomicAdd(&g_done[blockIdx.x], 1u) + 1u;
        const int ylo = max(ty - 1, 0), yhi = min(ty + 1, GRID_N - 1);
        const int xlo = max(tx - 1, 0), xhi = min(tx + 1, GRID_N - 1);
        const unsigned base = (unsigned)(b << 6);
        for (int yy = ylo; yy <= yhi; yy++)
            for (int xx = xlo; xx <= xhi; xx++) {
                if (yy == ty && xx == tx) continue;
                volatile unsigned* d = &g_done[base + yy * GRID_N + xx];
                while (*d < target) __nanosleep(32);
            }
        __threadfence();                   // acquire neighbors' LUT stores
    }
    __syncthreads();

    // stage 4 quadrant tables from 9 LUT vectors (own LUT from register)
    float4* T = (float4*)smem_raw;        // T[quadrant*256 + bin]
    {
        const int ya0 = max(ty - 1, 0), ya1 = ty, yb1 = min(ty + 1, GRID_N - 1);
        const int xa0 = max(tx - 1, 0), xa1 = tx, xb1 = min(tx + 1, GRID_N - 1);
        const float* lb = g_luts + ((size_t)b << 14);
        float l00 = ldcg_f(lb + ((ya0 * GRID_N + xa0) << 8) + t);
        float l01 = ldcg_f(lb + ((ya0 * GRID_N + xa1) << 8) + t);
        float l02 = ldcg_f(lb + ((ya0 * GRID_N + xb1) << 8) + t);
        float l10 = ldcg_f(lb + ((ya1 * GRID_N + xa0) << 8) + t);
        float l11 = lut;                   // this tile's own LUT
        float l12 = ldcg_f(lb + ((ya1 * GRID_N + xb1) << 8) + t);
        float l20 = ldcg_f(lb + ((yb1 * GRID_N + xa0) << 8) + t);
        float l21 = ldcg_f(lb + ((yb1 * GRID_N + xa1) << 8) + t);
        float l22 = ldcg_f(lb + ((yb1 * GRID_N + xb1) << 8) + t);
        T[0 * NBINS + t] = make_float4(l00, l01, l10, l11);   // qy=0, qx=0
        T[1 * NBINS + t] = make_float4(l01, l02, l11, l12);   // qy=0, qx=1
        T[2 * NBINS + t] = make_float4(l10, l11, l20, l21);   // qy=1, qx=0
        T[3 * NBINS + t] = make_float4(l11, l12, l21, l22);   // qy=1, qx=1
    }
    __syncthreads();

    // apply from retained bins (no input re-read)
    const int qx = j >> 5;
    const float fx = (qx ? ((float)j - 31.5f) : ((float)j + 32.5f)) * (1.0f / TILE);

    const float4* Ta = T + qx * NBINS;          // rows i < 32 (qy=0)
    const float4* Tb = T + (2 + qx) * NBINS;    // rows i >= 32 (qy=1)

    float* q = q0;
    float fy = ((float)i0 + 32.5f) * (1.0f / TILE);   // exact dyadic
    #pragma unroll
    for (int k = 0; k < 8; k++) {
        int bin = (packed[k >> 2] >> ((k & 3) * 8)) & 255;
        float4 tt = Ta[bin];
        float top = fmaf(fx, tt.y - tt.x, tt.x);
        float bot = fmaf(fx, tt.w - tt.z, tt.z);
        __stcs(q, fmaf(fy, bot - top, top));
        q += qstep; fy += (4.0f / TILE);
    }
    fy = ((float)i0 + 0.5f) * (1.0f / TILE);
    #pragma unroll
    for (int k = 8; k < 16; k++) {
        int bin = (packed[k >> 2] >> ((k & 3) * 8)) & 255;
        float4 tt = Tb[bin];
        float top = fmaf(fx, tt.y - tt.x, tt.x);
        float bot = fmaf(fx, tt.w - tt.z, tt.z);
        __stcs(q, fmaf(fy, bot - top, top));
        q += qstep; fy += (4.0f / TILE);
    }
}

extern "C" void kernel_launch(void* const* d_in, const int* in_sizes, int n_in,
                              void* d_out, int out_size) {
    const float* x          = (const float*)d_in[0];
    const int*   hflip      = (const int*)d_in[1];
    const int*   vflip      = (const int*)d_in[2];
    const int*   offy       = (const int*)d_in[3];
    const int*   offx       = (const int*)d_in[4];
    const int*   apply_clahe= (const int*)d_in[5];
    float*       out        = (float*)d_out;

    clahe_fused_kernel<<<NB * GRID_N * GRID_N, NBINS>>>(
        x, hflip, vflip, offy, offx, apply_clahe, out);
}